// round 7
// baseline (speedup 1.0000x reference)
#include <cuda_runtime.h>
#include <cstdint>

#define BH_N    128
#define M_TOTAL 512
#define L_SPAN  2048
#define HD      128
#define KV_LEN  (M_TOTAL + L_SPAN)   // 2560
#define BM      64
#define BN      64
#define NKT     33
#define NPOS    32                    // pos blocks: t < 32
#define THREADS 256                   // 8 warps: 4 row-groups x 2 column-halves

// SMEM strides (floats) chosen for conflict-free mma fragment loads
#define QS_STRIDE 132   // %32==4 -> A-frag bank = 4g+tg (distinct)
#define KS_STRIDE 132
#define VS_STRIDE 136   // %32==8 -> B-frag bank = 8tg+g (distinct)
#define PT_STRIDE 72    // %32==8
#define PB_STRIDE 72
#define RG_STRIDE 132

#define QS_OFF 0
#define KS_OFF (QS_OFF + BM * QS_STRIDE)
#define VS_OFF (KS_OFF + BN * KS_STRIDE)
#define PT_OFF (VS_OFF + BN * VS_STRIDE)
#define RG_OFF (PT_OFF + HD * PT_STRIDE)
#define PB_OFF (RG_OFF + BM * RG_STRIDE)
#define EX_OFF (PB_OFF + BM * PB_STRIDE)   // 2 x 64 exchange (max / sum)
#define SMEM_FLOATS (EX_OFF + 2 * BM)
#define SMEM_BYTES  (SMEM_FLOATS * 4)

__device__ __forceinline__ uint32_t f2tf(float x) {
    uint32_t r;
    asm("cvt.rna.tf32.f32 %0, %1;" : "=r"(r) : "f"(x));
    return r;
}

__device__ __forceinline__ void mma_tf32(float* d, const uint32_t* a, const uint32_t* b) {
    asm volatile(
        "mma.sync.aligned.m16n8k8.row.col.f32.tf32.tf32.f32 "
        "{%0,%1,%2,%3}, {%4,%5,%6,%7}, {%8,%9}, {%0,%1,%2,%3};\n"
        : "+f"(d[0]), "+f"(d[1]), "+f"(d[2]), "+f"(d[3])
        : "r"(a[0]), "r"(a[1]), "r"(a[2]), "r"(a[3]), "r"(b[0]), "r"(b[1]));
}

extern "C" __global__ void __launch_bounds__(THREADS, 1)
seq_attn_kernel(const float* __restrict__ Q, const float* __restrict__ K,
                const float* __restrict__ V, const float* __restrict__ PE,
                float* __restrict__ OUT)
{
    extern __shared__ float sm[];
    uint32_t* smu = reinterpret_cast<uint32_t*>(sm);

    const int tid  = threadIdx.x;
    const int warp = tid >> 5;
    const int lane = tid & 31;
    const int g    = lane >> 2;
    const int tg   = lane & 3;
    const int wg   = warp & 3;        // row group 0..3
    const int half = warp >> 2;       // column half 0..1
    const int wrow = wg * 16;
    const int ntb  = half * 4;        // QK/pos: this half's 4 n8-tiles (32 key cols)
    const int colb = half * 8;        // PV:     this half's 8 n8-tiles (64 out cols)
    const int m0   = blockIdx.x * BM;
    const int b    = blockIdx.y;

    const float qscale = 0.08838834764831845f;  // 1/sqrt(128) folded into Q

    // base pointers for staged loads
    const float* gkb = K + (size_t)b * KV_LEN * HD + (size_t)m0 * HD;
    const float* gvb = V + (size_t)b * KV_LEN * HD + (size_t)m0 * HD;
    const int pc = tid & 15, pr = tid >> 4;   // P-load mapping: 16 lanes x 16 rows

    // ---- load Q tile (scaled, tf32) ----
    {
        const float* gq = Q + ((size_t)b * M_TOTAL + m0) * HD;
        for (int r = warp; r < BM; r += 8) {
            float4 x = *reinterpret_cast<const float4*>(gq + r * HD + lane * 4);
            uint32_t* dst = smu + QS_OFF + r * QS_STRIDE + lane * 4;
            dst[0] = f2tf(x.x * qscale); dst[1] = f2tf(x.y * qscale);
            dst[2] = f2tf(x.z * qscale); dst[3] = f2tf(x.w * qscale);
        }
    }

    // ---- register staging for tile 0 ----
    float4 stK[8], stV[8], stP[8];
    {
#pragma unroll
        for (int i = 0; i < 8; ++i) {
            const int r = warp + 8 * i;
            stK[i] = *reinterpret_cast<const float4*>(gkb + r * HD + lane * 4);
            stV[i] = *reinterpret_cast<const float4*>(gvb + r * HD + lane * 4);
        }
#pragma unroll
        for (int i = 0; i < 8; ++i) {
            const int d = pr + 16 * i;
            stP[i] = *reinterpret_cast<const float4*>(PE + (size_t)d * L_SPAN + pc * 4);
        }
    }

    float O[8][4];
#pragma unroll
    for (int n = 0; n < 8; ++n)
#pragma unroll
        for (int e = 0; e < 4; ++e) O[n][e] = 0.f;

    float m0r = -1e30f, m1r = -1e30f;
    float l0r = 0.f,    l1r = 0.f;

    const int r0 = wrow + g, r1 = wrow + g + 8;

    for (int t = 0; t < NKT; ++t) {
        const bool do_pos = (t < NPOS);

        // ---- publish staged tile t to SMEM (buffers free from t-1) ----
#pragma unroll
        for (int i = 0; i < 8; ++i) {
            const int r = warp + 8 * i;
            uint32_t* dk = smu + KS_OFF + r * KS_STRIDE + lane * 4;
            dk[0] = f2tf(stK[i].x); dk[1] = f2tf(stK[i].y);
            dk[2] = f2tf(stK[i].z); dk[3] = f2tf(stK[i].w);
            uint32_t* dv = smu + VS_OFF + r * VS_STRIDE + lane * 4;
            dv[0] = f2tf(stV[i].x); dv[1] = f2tf(stV[i].y);
            dv[2] = f2tf(stV[i].z); dv[3] = f2tf(stV[i].w);
        }
        if (do_pos) {
#pragma unroll
            for (int i = 0; i < 8; ++i) {
                const int d = pr + 16 * i;
                uint32_t* dp = smu + PT_OFF + d * PT_STRIDE + pc * 4;
                dp[0] = f2tf(stP[i].x); dp[1] = f2tf(stP[i].y);
                dp[2] = f2tf(stP[i].z); dp[3] = f2tf(stP[i].w);
            }
        }
        __syncthreads();   // S1: tile t visible everywhere

        // ---- issue LDGs for tile t+1 into registers (hidden under QK) ----
        if (t + 1 < NKT) {
            const float* gk = gkb + (size_t)(t + 1) * BN * HD;
            const float* gv = gvb + (size_t)(t + 1) * BN * HD;
#pragma unroll
            for (int i = 0; i < 8; ++i) {
                const int r = warp + 8 * i;
                stK[i] = *reinterpret_cast<const float4*>(gk + r * HD + lane * 4);
                stV[i] = *reinterpret_cast<const float4*>(gv + r * HD + lane * 4);
            }
            if (t + 1 < NPOS) {
                const float* gp = PE + (t + 1) * BN;
#pragma unroll
                for (int i = 0; i < 8; ++i) {
                    const int d = pr + 16 * i;
                    stP[i] = *reinterpret_cast<const float4*>(gp + (size_t)d * L_SPAN + pc * 4);
                }
            }
        }

        // ---- S = Q @ K^T and Spos = Q @ Pblk (this half's 4 n-tiles) ----
        float s[4][4], sp[4][4];
#pragma unroll
        for (int n = 0; n < 4; ++n)
#pragma unroll
            for (int e = 0; e < 4; ++e) { s[n][e] = 0.f; sp[n][e] = 0.f; }

#pragma unroll 2
        for (int ks = 0; ks < 16; ++ks) {
            uint32_t a[4];
            const uint32_t* qb = smu + QS_OFF + r0 * QS_STRIDE + ks * 8 + tg;
            a[0] = qb[0];
            a[1] = qb[8 * QS_STRIDE];
            a[2] = qb[4];
            a[3] = qb[8 * QS_STRIDE + 4];
#pragma unroll
            for (int nt = 0; nt < 4; ++nt) {
                uint32_t bk[2];
                const uint32_t* kb = smu + KS_OFF + ((ntb + nt) * 8 + g) * KS_STRIDE + ks * 8 + tg;
                bk[0] = kb[0]; bk[1] = kb[4];
                mma_tf32(s[nt], a, bk);
            }
            if (do_pos) {
#pragma unroll
                for (int nt = 0; nt < 4; ++nt) {
                    uint32_t bp[2];
                    const uint32_t* pb = smu + PT_OFF + (ks * 8 + tg) * PT_STRIDE + (ntb + nt) * 8 + g;
                    bp[0] = pb[0]; bp[1] = pb[4 * PT_STRIDE];
                    mma_tf32(sp[nt], a, bp);
                }
            }
        }

        // ---- Spos -> ring buffer (halves write disjoint columns) ----
        if (do_pos) {
            const int base = (t & 1) * BN;
            float* rg = sm + RG_OFF;
#pragma unroll
            for (int nt = 0; nt < 4; ++nt) {
                const int c = (ntb + nt) * 8 + tg * 2;
                rg[r0 * RG_STRIDE + base + c]     = sp[nt][0];
                rg[r0 * RG_STRIDE + base + c + 1] = sp[nt][1];
                rg[r1 * RG_STRIDE + base + c]     = sp[nt][2];
                rg[r1 * RG_STRIDE + base + c + 1] = sp[nt][3];
            }
        }
        __syncthreads();   // S2: ring visible (cross-half reads)

        // ---- add positional logit (l = 64t + j - i), mask window ----
        {
            const float* rg = sm + RG_OFF;
#pragma unroll
            for (int nt = 0; nt < 4; ++nt) {
#pragma unroll
                for (int e = 0; e < 4; ++e) {
                    const int j = (ntb + nt) * 8 + tg * 2 + (e & 1);
                    const int r = (e < 2) ? r0 : r1;
                    const int l = t * BN + j - r;
                    if (l >= 0 && l < L_SPAN)
                        s[nt][e] += rg[r * RG_STRIDE + (l & 127)];
                    else
                        s[nt][e] = -1e30f;
                }
            }
        }

        // ---- online softmax: local max, then cross-half exchange ----
        float ml0 = -1e30f, ml1 = -1e30f;
#pragma unroll
        for (int nt = 0; nt < 4; ++nt) {
            ml0 = fmaxf(ml0, fmaxf(s[nt][0], s[nt][1]));
            ml1 = fmaxf(ml1, fmaxf(s[nt][2], s[nt][3]));
        }
        ml0 = fmaxf(ml0, __shfl_xor_sync(0xffffffffu, ml0, 1));
        ml0 = fmaxf(ml0, __shfl_xor_sync(0xffffffffu, ml0, 2));
        ml1 = fmaxf(ml1, __shfl_xor_sync(0xffffffffu, ml1, 1));
        ml1 = fmaxf(ml1, __shfl_xor_sync(0xffffffffu, ml1, 2));

        float* ex = sm + EX_OFF;
        if (tg == 0) {
            ex[half * BM + r0] = ml0;
            ex[half * BM + r1] = ml1;
        }
        __syncthreads();   // S3: exchange visible
        ml0 = fmaxf(ml0, ex[(1 - half) * BM + r0]);
        ml1 = fmaxf(ml1, ex[(1 - half) * BM + r1]);

        const float mn0 = fmaxf(m0r, ml0);
        const float mn1 = fmaxf(m1r, ml1);
        const float al0 = __expf(m0r - mn0);
        const float al1 = __expf(m1r - mn1);
        m0r = mn0; m1r = mn1;

        float ps0 = 0.f, ps1 = 0.f;
#pragma unroll
        for (int nt = 0; nt < 4; ++nt) {
            s[nt][0] = __expf(s[nt][0] - mn0);
            s[nt][1] = __expf(s[nt][1] - mn0);
            s[nt][2] = __expf(s[nt][2] - mn1);
            s[nt][3] = __expf(s[nt][3] - mn1);
            ps0 += s[nt][0] + s[nt][1];
            ps1 += s[nt][2] + s[nt][3];
        }
        l0r = l0r * al0 + ps0;
        l1r = l1r * al1 + ps1;

#pragma unroll
        for (int n = 0; n < 8; ++n) {
            O[n][0] *= al0; O[n][1] *= al0;
            O[n][2] *= al1; O[n][3] *= al1;
        }

        // ---- probs -> dedicated PB buffer ----
        {
            uint32_t* pu = smu + PB_OFF;
#pragma unroll
            for (int nt = 0; nt < 4; ++nt) {
                const int c = (ntb + nt) * 8 + tg * 2;
                pu[r0 * PB_STRIDE + c]     = f2tf(s[nt][0]);
                pu[r0 * PB_STRIDE + c + 1] = f2tf(s[nt][1]);
                pu[r1 * PB_STRIDE + c]     = f2tf(s[nt][2]);
                pu[r1 * PB_STRIDE + c + 1] = f2tf(s[nt][3]);
            }
        }
        __syncthreads();   // S4: probs visible

        // ---- O += P @ V (this half's 64 output columns) ----
#pragma unroll 2
        for (int ks = 0; ks < 8; ++ks) {
            uint32_t a[4];
            const uint32_t* pb = smu + PB_OFF + r0 * PB_STRIDE + ks * 8 + tg;
            a[0] = pb[0];
            a[1] = pb[8 * PB_STRIDE];
            a[2] = pb[4];
            a[3] = pb[8 * PB_STRIDE + 4];
#pragma unroll
            for (int nt = 0; nt < 8; ++nt) {
                uint32_t bv[2];
                const uint32_t* vb = smu + VS_OFF + (ks * 8 + tg) * VS_STRIDE + (colb + nt) * 8 + g;
                bv[0] = vb[0]; bv[1] = vb[4 * VS_STRIDE];
                mma_tf32(O[nt], a, bv);
            }
        }
        __syncthreads();   // S5: PV done -> K/V/P buffers free for next publish
    }

    // ---- epilogue: cross-half sumexp reduction, normalize, store ----
    l0r += __shfl_xor_sync(0xffffffffu, l0r, 1);
    l0r += __shfl_xor_sync(0xffffffffu, l0r, 2);
    l1r += __shfl_xor_sync(0xffffffffu, l1r, 1);
    l1r += __shfl_xor_sync(0xffffffffu, l1r, 2);

    float* ex = sm + EX_OFF;
    if (tg == 0) {
        ex[half * BM + r0] = l0r;
        ex[half * BM + r1] = l1r;
    }
    __syncthreads();
    const float i0 = 1.f / (l0r + ex[(1 - half) * BM + r0]);
    const float i1 = 1.f / (l1r + ex[(1 - half) * BM + r1]);

    float* go = OUT + ((size_t)b * M_TOTAL + m0) * HD;
#pragma unroll
    for (int nt = 0; nt < 8; ++nt) {
        const int c = (colb + nt) * 8 + tg * 2;
        float2 o0 = make_float2(O[nt][0] * i0, O[nt][1] * i0);
        *reinterpret_cast<float2*>(go + r0 * HD + c) = o0;
        float2 o1 = make_float2(O[nt][2] * i1, O[nt][3] * i1);
        *reinterpret_cast<float2*>(go + r1 * HD + c) = o1;
    }
}

extern "C" void kernel_launch(void* const* d_in, const int* in_sizes, int n_in,
                              void* d_out, int out_size) {
    const float* q  = (const float*)d_in[0];
    const float* k  = (const float*)d_in[1];
    const float* v  = (const float*)d_in[2];
    const float* pe = (const float*)d_in[3];
    float* out = (float*)d_out;

    cudaFuncSetAttribute(seq_attn_kernel,
                         cudaFuncAttributeMaxDynamicSharedMemorySize, SMEM_BYTES);

    dim3 grid(M_TOTAL / BM, BH_N);
    seq_attn_kernel<<<grid, THREADS, SMEM_BYTES>>>(q, k, v, pe, out);
}

// round 8
// speedup vs baseline: 2.8543x; 2.8543x over previous
#include <cuda_runtime.h>
#include <cuda_fp16.h>
#include <cstdint>

#define BH_N    128
#define M_TOTAL 512
#define L_SPAN  2048
#define HD      128
#define KV_LEN  (M_TOTAL + L_SPAN)   // 2560
#define BM      64
#define BN      64
#define NKT     33
#define NPOS    32
#define THREADS 256                   // 8 warps: 4 row-groups x 2 column-halves

// ---------------- fp16 pre-converted global scratch ----------------
__device__ __half d_QH[(size_t)BH_N * M_TOTAL * HD];   // Q * 1/sqrt(128)
__device__ __half d_KH[(size_t)BH_N * KV_LEN * HD];    // K [b][k][d]
__device__ __half d_VT[(size_t)BH_N * HD * KV_LEN];    // V transposed [b][d][k]
__device__ __half d_PET[(size_t)L_SPAN * HD];          // PE transposed [l][d]

// ---------------- SMEM layout (half indices) ----------------
// 136-half rows (68 words, 68%32==4) for 128-wide tiles; 72-half rows (36 words) for 64-wide.
#define QS_H 0                       // 64 x 136
#define KS_H (QS_H + BM * 136)       // 64 x 136
#define VT_H (KS_H + BN * 136)       // 128 x 72 (VT[d][k])
#define PL_H (VT_H + HD * 72)        // 64 x 136 (PET rows)
#define PB_H (PL_H + BM * 136)       // 64 x 72 (probs)
#define RG_H (PB_H + BM * 72)        // ring fp32 from here
#define RG_F (RG_H / 2)              // float index of ring
#define EX_F (RG_F + BM * 132)       // 2 x 64 float exchange
#define SMEM_BYTES ((EX_F + 2 * BM) * 4)   // 114176

__device__ __forceinline__ void mma_f16(float* d, const uint32_t* a, const uint32_t* b) {
    asm volatile(
        "mma.sync.aligned.m16n8k16.row.col.f32.f16.f16.f32 "
        "{%0,%1,%2,%3}, {%4,%5,%6,%7}, {%8,%9}, {%0,%1,%2,%3};\n"
        : "+f"(d[0]), "+f"(d[1]), "+f"(d[2]), "+f"(d[3])
        : "r"(a[0]), "r"(a[1]), "r"(a[2]), "r"(a[3]), "r"(b[0]), "r"(b[1]));
}

#define CP16(dst_sh, src) \
    asm volatile("cp.async.cg.shared.global [%0], [%1], 16;\n" :: "r"(dst_sh), "l"(src))
#define CP_COMMIT() asm volatile("cp.async.commit_group;\n" ::: "memory")
#define CP_WAIT0()  asm volatile("cp.async.wait_group 0;\n" ::: "memory")

// ---------------- pre-pass kernels ----------------
__global__ void cvtQ_kernel(const float* __restrict__ q) {
    size_t i = (size_t)blockIdx.x * 256 + threadIdx.x;
    const float s = 0.08838834764831845f;
    float4 v = reinterpret_cast<const float4*>(q)[i];
    __half2* o = reinterpret_cast<__half2*>(d_QH);
    o[2 * i]     = __floats2half2_rn(v.x * s, v.y * s);
    o[2 * i + 1] = __floats2half2_rn(v.z * s, v.w * s);
}
__global__ void cvtK_kernel(const float* __restrict__ k) {
    size_t i = (size_t)blockIdx.x * 256 + threadIdx.x;
    float4 v = reinterpret_cast<const float4*>(k)[i];
    __half2* o = reinterpret_cast<__half2*>(d_KH);
    o[2 * i]     = __floats2half2_rn(v.x, v.y);
    o[2 * i + 1] = __floats2half2_rn(v.z, v.w);
}
__global__ void transV_kernel(const float* __restrict__ V) {
    __shared__ float tile[32][33];
    int b = blockIdx.z, k0 = blockIdx.x * 32, d0 = blockIdx.y * 32;
    int tx = threadIdx.x, ty = threadIdx.y;
    const float* src = V + ((size_t)b * KV_LEN + k0) * HD + d0;
#pragma unroll
    for (int i = 0; i < 32; i += 8) tile[ty + i][tx] = src[(size_t)(ty + i) * HD + tx];
    __syncthreads();
    __half* dst = d_VT + ((size_t)b * HD + d0) * KV_LEN + k0;
#pragma unroll
    for (int i = 0; i < 32; i += 8)
        dst[(size_t)(ty + i) * KV_LEN + tx] = __float2half(tile[tx][ty + i]);
}
__global__ void transPE_kernel(const float* __restrict__ PE) {
    __shared__ float tile[32][33];
    int l0 = blockIdx.x * 32, d0 = blockIdx.y * 32;
    int tx = threadIdx.x, ty = threadIdx.y;
#pragma unroll
    for (int i = 0; i < 32; i += 8)
        tile[ty + i][tx] = PE[(size_t)(d0 + ty + i) * L_SPAN + l0 + tx];
    __syncthreads();
#pragma unroll
    for (int i = 0; i < 32; i += 8)
        d_PET[(size_t)(l0 + ty + i) * HD + d0 + tx] = __float2half(tile[tx][ty + i]);
}

// ---------------- main kernel ----------------
extern "C" __global__ void __launch_bounds__(THREADS, 2)
seq_attn_kernel(float* __restrict__ OUT)
{
    extern __shared__ __align__(16) char smraw[];
    __half*   smH = reinterpret_cast<__half*>(smraw);
    uint32_t* smW = reinterpret_cast<uint32_t*>(smraw);
    float*    smF = reinterpret_cast<float*>(smraw);

    const int tid  = threadIdx.x;
    const int warp = tid >> 5;
    const int lane = tid & 31;
    const int g    = lane >> 2;
    const int tg   = lane & 3;
    const int wg   = warp & 3;
    const int half = warp >> 2;
    const int wrow = wg * 16;
    const int ntb  = half * 4;        // QK/pos: 4 n8-tiles (32 key cols)
    const int colb = half * 8;        // PV: 8 n8-tiles (64 out dims)
    const int m0   = blockIdx.x * BM;
    const int b    = blockIdx.y;

    const int c16 = tid & 15, r16 = tid >> 4;   // 16 chunks x 16 rows mapping
    const int c8  = tid & 7,  r8  = tid >> 3;   // 8 chunks x 32 rows mapping

    const __half* gK  = d_KH + ((size_t)b * KV_LEN + m0) * HD;
    const __half* gVT = d_VT + (size_t)b * HD * KV_LEN + m0;

    // helpers to issue one tile's cp.asyncs
    auto issueK = [&](int t) {
#pragma unroll
        for (int i = 0; i < 4; ++i) {
            const int r = r16 + 16 * i;
            uint32_t dst = (uint32_t)__cvta_generic_to_shared(smH + KS_H + r * 136 + 8 * c16);
            CP16(dst, gK + ((size_t)t * BN + r) * HD + 8 * c16);
        }
    };
    auto issueV = [&](int t) {
#pragma unroll
        for (int i = 0; i < 4; ++i) {
            const int d = r8 + 32 * i;
            uint32_t dst = (uint32_t)__cvta_generic_to_shared(smH + VT_H + d * 72 + 8 * c8);
            CP16(dst, gVT + (size_t)d * KV_LEN + t * BN + 8 * c8);
        }
    };
    auto issueP = [&](int t) {
#pragma unroll
        for (int i = 0; i < 4; ++i) {
            const int r = r16 + 16 * i;
            uint32_t dst = (uint32_t)__cvta_generic_to_shared(smH + PL_H + r * 136 + 8 * c16);
            CP16(dst, d_PET + ((size_t)t * BN + r) * HD + 8 * c16);
        }
    };

    // ---- prologue: Q + tile0 ----
    {
        const __half* gq = d_QH + ((size_t)b * M_TOTAL + m0) * HD;
#pragma unroll
        for (int i = 0; i < 4; ++i) {
            const int r = r16 + 16 * i;
            uint32_t dst = (uint32_t)__cvta_generic_to_shared(smH + QS_H + r * 136 + 8 * c16);
            CP16(dst, gq + (size_t)r * HD + 8 * c16);
        }
        issueK(0); issueV(0); issueP(0);
        CP_COMMIT();
    }
    CP_WAIT0();
    __syncthreads();

    float O[8][4];
#pragma unroll
    for (int n = 0; n < 8; ++n)
#pragma unroll
        for (int e = 0; e < 4; ++e) O[n][e] = 0.f;

    float m0r = -1e30f, m1r = -1e30f;
    float l0r = 0.f,    l1r = 0.f;

    const int r0 = wrow + g, r1 = wrow + g + 8;
    const uint32_t* Wq = smW + (QS_H >> 1);
    const uint32_t* Wk = smW + (KS_H >> 1);
    const uint32_t* Wl = smW + (PL_H >> 1);
    const uint32_t* Wv = smW + (VT_H >> 1);
    uint32_t* Wpb = smW + (PB_H >> 1);

    for (int t = 0; t < NKT; ++t) {
        const bool do_pos = (t < NPOS);

        // ---- S = Q @ K^T and Spos = Q @ PET (8 k16 steps) ----
        float s[4][4], sp[4][4];
#pragma unroll
        for (int n = 0; n < 4; ++n)
#pragma unroll
            for (int e = 0; e < 4; ++e) { s[n][e] = 0.f; sp[n][e] = 0.f; }

#pragma unroll 2
        for (int ks = 0; ks < 8; ++ks) {
            const int ao = ks * 8 + tg;
            uint32_t a[4];
            a[0] = Wq[r0 * 68 + ao];
            a[1] = Wq[(r0 + 8) * 68 + ao];
            a[2] = Wq[r0 * 68 + ao + 4];
            a[3] = Wq[(r0 + 8) * 68 + ao + 4];
#pragma unroll
            for (int nt = 0; nt < 4; ++nt) {
                const int n = (ntb + nt) * 8 + g;
                uint32_t bk[2] = { Wk[n * 68 + ao], Wk[n * 68 + ao + 4] };
                mma_f16(s[nt], a, bk);
            }
            if (do_pos) {
#pragma unroll
                for (int nt = 0; nt < 4; ++nt) {
                    const int n = (ntb + nt) * 8 + g;
                    uint32_t bp[2] = { Wl[n * 68 + ao], Wl[n * 68 + ao + 4] };
                    mma_f16(sp[nt], a, bp);
                }
            }
        }

        // ---- Spos -> fp32 ring (halves write disjoint columns) ----
        if (do_pos) {
            const int base = (t & 1) * BN;
            float* rg = smF + RG_F;
#pragma unroll
            for (int nt = 0; nt < 4; ++nt) {
                const int c = (ntb + nt) * 8 + tg * 2;
                rg[r0 * 132 + base + c]     = sp[nt][0];
                rg[r0 * 132 + base + c + 1] = sp[nt][1];
                rg[r1 * 132 + base + c]     = sp[nt][2];
                rg[r1 * 132 + base + c + 1] = sp[nt][3];
            }
        }
        __syncthreads();   // S2: QK done for all -> K/PL buffers free; ring visible

        // ---- prefetch K/P for t+1 (latency hidden by softmax + PV) ----
        if (t + 1 < NKT) {
            issueK(t + 1);
            if (t + 1 < NPOS) issueP(t + 1);
            CP_COMMIT();
        }

        // ---- add positional logit (l = 64t + j - i), mask window ----
        {
            const float* rg = smF + RG_F;
#pragma unroll
            for (int nt = 0; nt < 4; ++nt) {
#pragma unroll
                for (int e = 0; e < 4; ++e) {
                    const int j = (ntb + nt) * 8 + tg * 2 + (e & 1);
                    const int r = (e < 2) ? r0 : r1;
                    const int l = t * BN + j - r;
                    if (l >= 0 && l < L_SPAN)
                        s[nt][e] += rg[r * 132 + (l & 127)];
                    else
                        s[nt][e] = -1e30f;
                }
            }
        }

        // ---- online softmax ----
        float ml0 = -1e30f, ml1 = -1e30f;
#pragma unroll
        for (int nt = 0; nt < 4; ++nt) {
            ml0 = fmaxf(ml0, fmaxf(s[nt][0], s[nt][1]));
            ml1 = fmaxf(ml1, fmaxf(s[nt][2], s[nt][3]));
        }
        ml0 = fmaxf(ml0, __shfl_xor_sync(0xffffffffu, ml0, 1));
        ml0 = fmaxf(ml0, __shfl_xor_sync(0xffffffffu, ml0, 2));
        ml1 = fmaxf(ml1, __shfl_xor_sync(0xffffffffu, ml1, 1));
        ml1 = fmaxf(ml1, __shfl_xor_sync(0xffffffffu, ml1, 2));

        float* ex = smF + EX_F;
        if (tg == 0) { ex[half * BM + r0] = ml0; ex[half * BM + r1] = ml1; }
        __syncthreads();   // S3
        ml0 = fmaxf(ml0, ex[(1 - half) * BM + r0]);
        ml1 = fmaxf(ml1, ex[(1 - half) * BM + r1]);

        const float mn0 = fmaxf(m0r, ml0);
        const float mn1 = fmaxf(m1r, ml1);
        const float al0 = __expf(m0r - mn0);
        const float al1 = __expf(m1r - mn1);
        m0r = mn0; m1r = mn1;

        float ps0 = 0.f, ps1 = 0.f;
#pragma unroll
        for (int nt = 0; nt < 4; ++nt) {
            s[nt][0] = __expf(s[nt][0] - mn0);
            s[nt][1] = __expf(s[nt][1] - mn0);
            s[nt][2] = __expf(s[nt][2] - mn1);
            s[nt][3] = __expf(s[nt][3] - mn1);
            ps0 += s[nt][0] + s[nt][1];
            ps1 += s[nt][2] + s[nt][3];
        }
        l0r = l0r * al0 + ps0;
        l1r = l1r * al1 + ps1;

#pragma unroll
        for (int n = 0; n < 8; ++n) {
            O[n][0] *= al0; O[n][1] *= al0;
            O[n][2] *= al1; O[n][3] *= al1;
        }

        // ---- probs -> PB (half2) ----
#pragma unroll
        for (int nt = 0; nt < 4; ++nt) {
            const int wi = (ntb + nt) * 4 + tg;
            __half2 h0 = __floats2half2_rn(s[nt][0], s[nt][1]);
            __half2 h1 = __floats2half2_rn(s[nt][2], s[nt][3]);
            Wpb[r0 * 36 + wi] = *reinterpret_cast<uint32_t*>(&h0);
            Wpb[r1 * 36 + wi] = *reinterpret_cast<uint32_t*>(&h1);
        }
        __syncthreads();   // S4: probs visible

        // ---- O += P @ V (4 k16 steps over 64 keys; B from VT[d][k]) ----
#pragma unroll 2
        for (int ks = 0; ks < 4; ++ks) {
            const int ao = ks * 8 + tg;
            uint32_t a[4];
            a[0] = Wpb[r0 * 36 + ao];
            a[1] = Wpb[(r0 + 8) * 36 + ao];
            a[2] = Wpb[r0 * 36 + ao + 4];
            a[3] = Wpb[(r0 + 8) * 36 + ao + 4];
#pragma unroll
            for (int nt = 0; nt < 8; ++nt) {
                const int n = (colb + nt) * 8 + g;
                uint32_t bv[2] = { Wv[n * 36 + ao], Wv[n * 36 + ao + 4] };
                mma_f16(O[nt], a, bv);
            }
        }
        __syncthreads();   // S5: V buffer free

        if (t + 1 < NKT) { issueV(t + 1); CP_COMMIT(); }
        CP_WAIT0();
        __syncthreads();   // S1: tile t+1 resident
    }

    // ---- epilogue ----
    l0r += __shfl_xor_sync(0xffffffffu, l0r, 1);
    l0r += __shfl_xor_sync(0xffffffffu, l0r, 2);
    l1r += __shfl_xor_sync(0xffffffffu, l1r, 1);
    l1r += __shfl_xor_sync(0xffffffffu, l1r, 2);

    float* ex = smF + EX_F;
    if (tg == 0) { ex[half * BM + r0] = l0r; ex[half * BM + r1] = l1r; }
    __syncthreads();
    const float i0 = 1.f / (l0r + ex[(1 - half) * BM + r0]);
    const float i1 = 1.f / (l1r + ex[(1 - half) * BM + r1]);

    float* go = OUT + ((size_t)b * M_TOTAL + m0) * HD;
#pragma unroll
    for (int nt = 0; nt < 8; ++nt) {
        const int c = (colb + nt) * 8 + tg * 2;
        *reinterpret_cast<float2*>(go + r0 * HD + c) = make_float2(O[nt][0] * i0, O[nt][1] * i0);
        *reinterpret_cast<float2*>(go + r1 * HD + c) = make_float2(O[nt][2] * i1, O[nt][3] * i1);
    }
}

extern "C" void kernel_launch(void* const* d_in, const int* in_sizes, int n_in,
                              void* d_out, int out_size) {
    const float* q  = (const float*)d_in[0];
    const float* k  = (const float*)d_in[1];
    const float* v  = (const float*)d_in[2];
    const float* pe = (const float*)d_in[3];
    float* out = (float*)d_out;

    cvtQ_kernel<<<(BH_N * M_TOTAL * HD / 4) / 256, 256>>>(q);
    cvtK_kernel<<<(size_t)(BH_N * KV_LEN * HD / 4) / 256, 256>>>(k);
    {
        dim3 gt(KV_LEN / 32, HD / 32, BH_N);
        transV_kernel<<<gt, dim3(32, 8)>>>(v);
    }
    {
        dim3 gp(L_SPAN / 32, HD / 32);
        transPE_kernel<<<gp, dim3(32, 8)>>>(pe);
    }

    cudaFuncSetAttribute(seq_attn_kernel,
                         cudaFuncAttributeMaxDynamicSharedMemorySize, SMEM_BYTES);
    dim3 grid(M_TOTAL / BM, BH_N);
    seq_attn_kernel<<<grid, THREADS, SMEM_BYTES>>>(out);
}

// round 9
// speedup vs baseline: 2.8745x; 1.0071x over previous
#include <cuda_runtime.h>
#include <cuda_fp16.h>
#include <cstdint>

#define BH_N    128
#define M_TOTAL 512
#define L_SPAN  2048
#define HD      128
#define KV_LEN  (M_TOTAL + L_SPAN)   // 2560
#define BM      64
#define BN      64
#define NKT     33
#define NPOS    32
#define THREADS 256                   // 8 warps: 2 row-groups x 4 column-quarters

// ---------------- fp16 pre-converted global scratch ----------------
__device__ __half d_QH[(size_t)BH_N * M_TOTAL * HD];   // Q * 1/sqrt(128)
__device__ __half d_KH[(size_t)BH_N * KV_LEN * HD];    // K [b][k][d]
__device__ __half d_VT[(size_t)BH_N * HD * KV_LEN];    // V transposed [b][d][k]
__device__ __half d_PET[(size_t)L_SPAN * HD];          // PE transposed [l][d]

// ---------------- SMEM layout (half indices) ----------------
#define QS_H 0                       // 64 x 136
#define KS_H (QS_H + BM * 136)
#define VT_H (KS_H + BN * 136)       // 128 x 72 (VT[d][k])
#define PL_H (VT_H + HD * 72)        // 64 x 136 (PET rows)
#define PB_H (PL_H + BM * 136)       // 64 x 72 (probs)
#define RG_H (PB_H + BM * 72)        // ring fp32 from here
#define RG_F (RG_H / 2)
#define EX_F (RG_F + BM * 132)       // 4 x 64 float exchange
#define SMEM_BYTES ((EX_F + 4 * BM) * 4)   // 114688

__device__ __forceinline__ void mma_f16(float* d, const uint32_t* a, const uint32_t* b) {
    asm volatile(
        "mma.sync.aligned.m16n8k16.row.col.f32.f16.f16.f32 "
        "{%0,%1,%2,%3}, {%4,%5,%6,%7}, {%8,%9}, {%0,%1,%2,%3};\n"
        : "+f"(d[0]), "+f"(d[1]), "+f"(d[2]), "+f"(d[3])
        : "r"(a[0]), "r"(a[1]), "r"(a[2]), "r"(a[3]), "r"(b[0]), "r"(b[1]));
}

#define CP16(dst_sh, src) \
    asm volatile("cp.async.cg.shared.global [%0], [%1], 16;\n" :: "r"(dst_sh), "l"(src))
#define CP_COMMIT() asm volatile("cp.async.commit_group;\n" ::: "memory")
#define CP_WAIT0()  asm volatile("cp.async.wait_group 0;\n" ::: "memory")

// ---------------- pre-pass kernels ----------------
__global__ void cvtQ_kernel(const float* __restrict__ q) {
    size_t i = (size_t)blockIdx.x * 256 + threadIdx.x;
    const float s = 0.08838834764831845f;
    float4 v = reinterpret_cast<const float4*>(q)[i];
    __half2* o = reinterpret_cast<__half2*>(d_QH);
    o[2 * i]     = __floats2half2_rn(v.x * s, v.y * s);
    o[2 * i + 1] = __floats2half2_rn(v.z * s, v.w * s);
}
__global__ void cvtK_kernel(const float* __restrict__ k) {
    size_t i = (size_t)blockIdx.x * 256 + threadIdx.x;
    float4 v = reinterpret_cast<const float4*>(k)[i];
    __half2* o = reinterpret_cast<__half2*>(d_KH);
    o[2 * i]     = __floats2half2_rn(v.x, v.y);
    o[2 * i + 1] = __floats2half2_rn(v.z, v.w);
}
__global__ void transV_kernel(const float* __restrict__ V) {
    __shared__ float tile[32][33];
    int b = blockIdx.z, k0 = blockIdx.x * 32, d0 = blockIdx.y * 32;
    int tx = threadIdx.x, ty = threadIdx.y;
    const float* src = V + ((size_t)b * KV_LEN + k0) * HD + d0;
#pragma unroll
    for (int i = 0; i < 32; i += 8) tile[ty + i][tx] = src[(size_t)(ty + i) * HD + tx];
    __syncthreads();
    __half* dst = d_VT + ((size_t)b * HD + d0) * KV_LEN + k0;
#pragma unroll
    for (int i = 0; i < 32; i += 8)
        dst[(size_t)(ty + i) * KV_LEN + tx] = __float2half(tile[tx][ty + i]);
}
__global__ void transPE_kernel(const float* __restrict__ PE) {
    __shared__ float tile[32][33];
    int l0 = blockIdx.x * 32, d0 = blockIdx.y * 32;
    int tx = threadIdx.x, ty = threadIdx.y;
#pragma unroll
    for (int i = 0; i < 32; i += 8)
        tile[ty + i][tx] = PE[(size_t)(d0 + ty + i) * L_SPAN + l0 + tx];
    __syncthreads();
#pragma unroll
    for (int i = 0; i < 32; i += 8)
        d_PET[(size_t)(l0 + ty + i) * HD + d0 + tx] = __float2half(tile[tx][ty + i]);
}

// ---------------- main kernel ----------------
extern "C" __global__ void __launch_bounds__(THREADS, 2)
seq_attn_kernel(float* __restrict__ OUT)
{
    extern __shared__ __align__(16) char smraw[];
    __half*   smH = reinterpret_cast<__half*>(smraw);
    uint32_t* smW = reinterpret_cast<uint32_t*>(smraw);
    float*    smF = reinterpret_cast<float*>(smraw);

    const int tid  = threadIdx.x;
    const int warp = tid >> 5;
    const int lane = tid & 31;
    const int g    = lane >> 2;
    const int tg   = lane & 3;
    const int rg   = warp & 1;        // row group 0..1 (32 rows each)
    const int qtr  = warp >> 1;       // column quarter 0..3
    const int m0   = blockIdx.x * BM;
    const int b    = blockIdx.y;

    const int rb0 = rg * 32;          // mt=0 m16-tile base
    const int rb1 = rg * 32 + 16;     // mt=1 m16-tile base
    const int kcb = qtr * 16;         // QK: this quarter's 16 key cols
    const int dcb = qtr * 32;         // PV: this quarter's 32 out dims

    const int c16 = tid & 15, r16 = tid >> 4;
    const int c8  = tid & 7,  r8  = tid >> 3;

    const __half* gK  = d_KH + ((size_t)b * KV_LEN + m0) * HD;
    const __half* gVT = d_VT + (size_t)b * HD * KV_LEN + m0;

    auto issueK = [&](int t) {
#pragma unroll
        for (int i = 0; i < 4; ++i) {
            const int r = r16 + 16 * i;
            uint32_t dst = (uint32_t)__cvta_generic_to_shared(smH + KS_H + r * 136 + 8 * c16);
            CP16(dst, gK + ((size_t)t * BN + r) * HD + 8 * c16);
        }
    };
    auto issueV = [&](int t) {
#pragma unroll
        for (int i = 0; i < 4; ++i) {
            const int d = r8 + 32 * i;
            uint32_t dst = (uint32_t)__cvta_generic_to_shared(smH + VT_H + d * 72 + 8 * c8);
            CP16(dst, gVT + (size_t)d * KV_LEN + t * BN + 8 * c8);
        }
    };
    auto issueP = [&](int t) {
#pragma unroll
        for (int i = 0; i < 4; ++i) {
            const int r = r16 + 16 * i;
            uint32_t dst = (uint32_t)__cvta_generic_to_shared(smH + PL_H + r * 136 + 8 * c16);
            CP16(dst, d_PET + ((size_t)t * BN + r) * HD + 8 * c16);
        }
    };

    // ---- prologue: Q + tile 0 ----
    {
        const __half* gq = d_QH + ((size_t)b * M_TOTAL + m0) * HD;
#pragma unroll
        for (int i = 0; i < 4; ++i) {
            const int r = r16 + 16 * i;
            uint32_t dst = (uint32_t)__cvta_generic_to_shared(smH + QS_H + r * 136 + 8 * c16);
            CP16(dst, gq + (size_t)r * HD + 8 * c16);
        }
        issueK(0); issueV(0); issueP(0);
        CP_COMMIT();
    }
    CP_WAIT0();
    __syncthreads();

    float O[2][4][4];                 // [mt][nt8][e]
#pragma unroll
    for (int mt = 0; mt < 2; ++mt)
#pragma unroll
        for (int n = 0; n < 4; ++n)
#pragma unroll
            for (int e = 0; e < 4; ++e) O[mt][n][e] = 0.f;

    float m_run[2][2] = {{-1e30f, -1e30f}, {-1e30f, -1e30f}};   // [mt][h]
    float l_run[2][2] = {{0.f, 0.f}, {0.f, 0.f}};

    const uint32_t* Wq = smW + (QS_H >> 1);
    const uint32_t* Wk = smW + (KS_H >> 1);
    const uint32_t* Wl = smW + (PL_H >> 1);
    const uint32_t* Wv = smW + (VT_H >> 1);
    uint32_t* Wpb = smW + (PB_H >> 1);

    for (int t = 0; t < NKT; ++t) {
        const bool do_pos = (t < NPOS);

        // ---- S = Q @ K^T, Spos = Q @ PET (8 k16 steps; 2 m-tiles x 2 n-tiles) ----
        float s[2][2][4], sp[2][2][4];
#pragma unroll
        for (int mt = 0; mt < 2; ++mt)
#pragma unroll
            for (int n = 0; n < 2; ++n)
#pragma unroll
                for (int e = 0; e < 4; ++e) { s[mt][n][e] = 0.f; sp[mt][n][e] = 0.f; }

#pragma unroll 2
        for (int ks = 0; ks < 8; ++ks) {
            const int ao = ks * 8 + tg;
            uint32_t a[2][4];
#pragma unroll
            for (int mt = 0; mt < 2; ++mt) {
                const int rr = rg * 32 + mt * 16 + g;
                a[mt][0] = Wq[rr * 68 + ao];
                a[mt][1] = Wq[(rr + 8) * 68 + ao];
                a[mt][2] = Wq[rr * 68 + ao + 4];
                a[mt][3] = Wq[(rr + 8) * 68 + ao + 4];
            }
#pragma unroll
            for (int nt = 0; nt < 2; ++nt) {
                const int n = kcb + nt * 8 + g;
                uint32_t bk[2] = { Wk[n * 68 + ao], Wk[n * 68 + ao + 4] };
                mma_f16(s[0][nt], a[0], bk);
                mma_f16(s[1][nt], a[1], bk);
            }
            if (do_pos) {
#pragma unroll
                for (int nt = 0; nt < 2; ++nt) {
                    const int n = kcb + nt * 8 + g;
                    uint32_t bp[2] = { Wl[n * 68 + ao], Wl[n * 68 + ao + 4] };
                    mma_f16(sp[0][nt], a[0], bp);
                    mma_f16(sp[1][nt], a[1], bp);
                }
            }
        }

        // ---- Spos -> fp32 ring ----
        if (do_pos) {
            const int base = (t & 1) * BN;
            float* rgb = smF + RG_F;
#pragma unroll
            for (int mt = 0; mt < 2; ++mt) {
                const int rr = rg * 32 + mt * 16 + g;
#pragma unroll
                for (int nt = 0; nt < 2; ++nt) {
                    const int c = kcb + nt * 8 + tg * 2;
                    rgb[rr * 132 + base + c]        = sp[mt][nt][0];
                    rgb[rr * 132 + base + c + 1]    = sp[mt][nt][1];
                    rgb[(rr + 8) * 132 + base + c]  = sp[mt][nt][2];
                    rgb[(rr + 8) * 132 + base + c + 1] = sp[mt][nt][3];
                }
            }
        }
        __syncthreads();   // S2: QK consumers done -> K/PL free; ring visible

        // ---- prefetch K/P for t+1 ----
        if (t + 1 < NKT) {
            issueK(t + 1);
            if (t + 1 < NPOS) issueP(t + 1);
            CP_COMMIT();
        }

        // ---- add positional logit, mask window ----
        {
            const float* rgb = smF + RG_F;
#pragma unroll
            for (int mt = 0; mt < 2; ++mt) {
#pragma unroll
                for (int nt = 0; nt < 2; ++nt) {
#pragma unroll
                    for (int e = 0; e < 4; ++e) {
                        const int j = kcb + nt * 8 + tg * 2 + (e & 1);
                        const int r = rg * 32 + mt * 16 + g + ((e < 2) ? 0 : 8);
                        const int l = t * BN + j - r;
                        if (l >= 0 && l < L_SPAN)
                            s[mt][nt][e] += rgb[r * 132 + (l & 127)];
                        else
                            s[mt][nt][e] = -1e30f;
                    }
                }
            }
        }

        // ---- online softmax: local max over quarter cols, cross-quarter exchange ----
        float ml[2][2];
#pragma unroll
        for (int mt = 0; mt < 2; ++mt) {
            ml[mt][0] = fmaxf(fmaxf(s[mt][0][0], s[mt][0][1]), fmaxf(s[mt][1][0], s[mt][1][1]));
            ml[mt][1] = fmaxf(fmaxf(s[mt][0][2], s[mt][0][3]), fmaxf(s[mt][1][2], s[mt][1][3]));
#pragma unroll
            for (int h = 0; h < 2; ++h) {
                ml[mt][h] = fmaxf(ml[mt][h], __shfl_xor_sync(0xffffffffu, ml[mt][h], 1));
                ml[mt][h] = fmaxf(ml[mt][h], __shfl_xor_sync(0xffffffffu, ml[mt][h], 2));
            }
        }
        float* ex = smF + EX_F;
        if (tg == 0) {
#pragma unroll
            for (int mt = 0; mt < 2; ++mt)
#pragma unroll
                for (int h = 0; h < 2; ++h)
                    ex[qtr * BM + rg * 32 + mt * 16 + h * 8 + g] = ml[mt][h];
        }
        __syncthreads();   // S3
#pragma unroll
        for (int mt = 0; mt < 2; ++mt)
#pragma unroll
            for (int h = 0; h < 2; ++h) {
                const int row = rg * 32 + mt * 16 + h * 8 + g;
#pragma unroll
                for (int qq = 0; qq < 4; ++qq)
                    ml[mt][h] = fmaxf(ml[mt][h], ex[qq * BM + row]);
            }

        float al[2][2];
#pragma unroll
        for (int mt = 0; mt < 2; ++mt)
#pragma unroll
            for (int h = 0; h < 2; ++h) {
                const float mn = fmaxf(m_run[mt][h], ml[mt][h]);
                al[mt][h] = __expf(m_run[mt][h] - mn);
                m_run[mt][h] = mn;
            }

#pragma unroll
        for (int mt = 0; mt < 2; ++mt) {
            float ps0 = 0.f, ps1 = 0.f;
#pragma unroll
            for (int nt = 0; nt < 2; ++nt) {
                s[mt][nt][0] = __expf(s[mt][nt][0] - m_run[mt][0]);
                s[mt][nt][1] = __expf(s[mt][nt][1] - m_run[mt][0]);
                s[mt][nt][2] = __expf(s[mt][nt][2] - m_run[mt][1]);
                s[mt][nt][3] = __expf(s[mt][nt][3] - m_run[mt][1]);
                ps0 += s[mt][nt][0] + s[mt][nt][1];
                ps1 += s[mt][nt][2] + s[mt][nt][3];
            }
            l_run[mt][0] = l_run[mt][0] * al[mt][0] + ps0;
            l_run[mt][1] = l_run[mt][1] * al[mt][1] + ps1;
#pragma unroll
            for (int n = 0; n < 4; ++n) {
                O[mt][n][0] *= al[mt][0]; O[mt][n][1] *= al[mt][0];
                O[mt][n][2] *= al[mt][1]; O[mt][n][3] *= al[mt][1];
            }
        }

        // ---- probs -> PB (half2) ----
#pragma unroll
        for (int mt = 0; mt < 2; ++mt) {
            const int rr = rg * 32 + mt * 16 + g;
#pragma unroll
            for (int nt = 0; nt < 2; ++nt) {
                const int wi = qtr * 8 + nt * 4 + tg;
                __half2 h0 = __floats2half2_rn(s[mt][nt][0], s[mt][nt][1]);
                __half2 h1 = __floats2half2_rn(s[mt][nt][2], s[mt][nt][3]);
                Wpb[rr * 36 + wi]       = *reinterpret_cast<uint32_t*>(&h0);
                Wpb[(rr + 8) * 36 + wi] = *reinterpret_cast<uint32_t*>(&h1);
            }
        }
        __syncthreads();   // S4: probs visible across quarters

        // ---- O += P @ V (4 k16 steps; this quarter's 32 out dims) ----
#pragma unroll 2
        for (int ks = 0; ks < 4; ++ks) {
            const int ao = ks * 8 + tg;
            uint32_t a[2][4];
#pragma unroll
            for (int mt = 0; mt < 2; ++mt) {
                const int rr = rg * 32 + mt * 16 + g;
                a[mt][0] = Wpb[rr * 36 + ao];
                a[mt][1] = Wpb[(rr + 8) * 36 + ao];
                a[mt][2] = Wpb[rr * 36 + ao + 4];
                a[mt][3] = Wpb[(rr + 8) * 36 + ao + 4];
            }
#pragma unroll
            for (int nt8 = 0; nt8 < 4; ++nt8) {
                const int n = dcb + nt8 * 8 + g;
                uint32_t bv[2] = { Wv[n * 36 + ao], Wv[n * 36 + ao + 4] };
                mma_f16(O[0][nt8], a[0], bv);
                mma_f16(O[1][nt8], a[1], bv);
            }
        }
        __syncthreads();   // S5: V buffer free

        if (t + 1 < NKT) { issueV(t + 1); CP_COMMIT(); }
        CP_WAIT0();
        __syncthreads();   // S1: tile t+1 resident
    }

    // ---- epilogue: quarter-sum reduction, normalize, store ----
#pragma unroll
    for (int mt = 0; mt < 2; ++mt)
#pragma unroll
        for (int h = 0; h < 2; ++h) {
            l_run[mt][h] += __shfl_xor_sync(0xffffffffu, l_run[mt][h], 1);
            l_run[mt][h] += __shfl_xor_sync(0xffffffffu, l_run[mt][h], 2);
        }
    float* ex = smF + EX_F;
    if (tg == 0) {
#pragma unroll
        for (int mt = 0; mt < 2; ++mt)
#pragma unroll
            for (int h = 0; h < 2; ++h)
                ex[qtr * BM + rg * 32 + mt * 16 + h * 8 + g] = l_run[mt][h];
    }
    __syncthreads();
    float inv[2][2];
#pragma unroll
    for (int mt = 0; mt < 2; ++mt)
#pragma unroll
        for (int h = 0; h < 2; ++h) {
            const int row = rg * 32 + mt * 16 + h * 8 + g;
            float tsum = 0.f;
#pragma unroll
            for (int qq = 0; qq < 4; ++qq) tsum += ex[qq * BM + row];
            inv[mt][h] = 1.f / tsum;
        }

    float* go = OUT + ((size_t)b * M_TOTAL + m0) * HD;
#pragma unroll
    for (int mt = 0; mt < 2; ++mt) {
        const int rr = rg * 32 + mt * 16 + g;
#pragma unroll
        for (int nt8 = 0; nt8 < 4; ++nt8) {
            const int c = dcb + nt8 * 8 + tg * 2;
            *reinterpret_cast<float2*>(go + rr * HD + c) =
                make_float2(O[mt][nt8][0] * inv[mt][0], O[mt][nt8][1] * inv[mt][0]);
            *reinterpret_cast<float2*>(go + (rr + 8) * HD + c) =
                make_float2(O[mt][nt8][2] * inv[mt][1], O[mt][nt8][3] * inv[mt][1]);
        }
    }
}

extern "C" void kernel_launch(void* const* d_in, const int* in_sizes, int n_in,
                              void* d_out, int out_size) {
    const float* q  = (const float*)d_in[0];
    const float* k  = (const float*)d_in[1];
    const float* v  = (const float*)d_in[2];
    const float* pe = (const float*)d_in[3];
    float* out = (float*)d_out;

    cvtQ_kernel<<<(BH_N * M_TOTAL * HD / 4) / 256, 256>>>(q);
    cvtK_kernel<<<(size_t)(BH_N * KV_LEN * HD / 4) / 256, 256>>>(k);
    {
        dim3 gt(KV_LEN / 32, HD / 32, BH_N);
        transV_kernel<<<gt, dim3(32, 8)>>>(v);
    }
    {
        dim3 gp(L_SPAN / 32, HD / 32);
        transPE_kernel<<<gp, dim3(32, 8)>>>(pe);
    }

    cudaFuncSetAttribute(seq_attn_kernel,
                         cudaFuncAttributeMaxDynamicSharedMemorySize, SMEM_BYTES);
    dim3 grid(M_TOTAL / BM, BH_N);
    seq_attn_kernel<<<grid, THREADS, SMEM_BYTES>>>(out);
}

// round 11
// speedup vs baseline: 3.3156x; 1.1534x over previous
#include <cuda_runtime.h>
#include <cuda_fp16.h>
#include <cstdint>

#define BH_N    128
#define M_TOTAL 512
#define L_SPAN  2048
#define HD      128
#define KV_LEN  (M_TOTAL + L_SPAN)   // 2560
#define BM      64
#define BN      64
#define NKT     33
#define NPOS    32
#define THREADS 256                   // 8 warps: 2 row-groups x 4 column-quarters

// ---------------- fp16 pre-converted global scratch ----------------
__device__ __half d_QH[(size_t)BH_N * M_TOTAL * HD];   // Q * 1/sqrt(128)
__device__ __half d_KH[(size_t)BH_N * KV_LEN * HD];    // K [b][k][d]
__device__ __half d_VT[(size_t)BH_N * HD * KV_LEN];    // V transposed [b][d][k]
__device__ __half d_PET[(size_t)L_SPAN * HD];          // PE transposed [l][d]

// ---------------- SMEM layout (half indices) ----------------
#define QS_H 0                       // 64 x 136
#define KS_H (QS_H + BM * 136)
#define VT_H (KS_H + BN * 136)       // 128 x 72 (VT[d][k])
#define PL_H (VT_H + HD * 72)        // 64 x 136 (PET rows)
#define PB_H (PL_H + BM * 136)       // 64 x 72 (probs)
#define RG_H (PB_H + BM * 72)        // ring fp32 from here
#define RG_F (RG_H / 2)
#define EX_F (RG_F + BM * 132)       // 4 x 64 float exchange
#define SMEM_BYTES ((EX_F + 4 * BM) * 4)   // 114688

__device__ __forceinline__ void mma_f16(float* d, const uint32_t* a, const uint32_t* b) {
    asm volatile(
        "mma.sync.aligned.m16n8k16.row.col.f32.f16.f16.f32 "
        "{%0,%1,%2,%3}, {%4,%5,%6,%7}, {%8,%9}, {%0,%1,%2,%3};\n"
        : "+f"(d[0]), "+f"(d[1]), "+f"(d[2]), "+f"(d[3])
        : "r"(a[0]), "r"(a[1]), "r"(a[2]), "r"(a[3]), "r"(b[0]), "r"(b[1]));
}

#define LDSM4(r, addr) \
    asm volatile("ldmatrix.sync.aligned.m8n8.x4.shared.b16 {%0,%1,%2,%3}, [%4];" \
        : "=r"((r)[0]), "=r"((r)[1]), "=r"((r)[2]), "=r"((r)[3]) : "r"(addr))

#define CP16(dst_sh, src) \
    asm volatile("cp.async.cg.shared.global [%0], [%1], 16;\n" :: "r"(dst_sh), "l"(src))
#define CP_COMMIT() asm volatile("cp.async.commit_group;\n" ::: "memory")
#define CP_WAIT0()  asm volatile("cp.async.wait_group 0;\n" ::: "memory")
#define CP_WAIT1()  asm volatile("cp.async.wait_group 1;\n" ::: "memory")

// ---------------- pre-pass kernels ----------------
__global__ void cvtQ_kernel(const float* __restrict__ q) {
    size_t i = (size_t)blockIdx.x * 256 + threadIdx.x;
    const float s = 0.08838834764831845f;
    float4 v = reinterpret_cast<const float4*>(q)[i];
    __half2* o = reinterpret_cast<__half2*>(d_QH);
    o[2 * i]     = __floats2half2_rn(v.x * s, v.y * s);
    o[2 * i + 1] = __floats2half2_rn(v.z * s, v.w * s);
}
__global__ void cvtK_kernel(const float* __restrict__ k) {
    size_t i = (size_t)blockIdx.x * 256 + threadIdx.x;
    float4 v = reinterpret_cast<const float4*>(k)[i];
    __half2* o = reinterpret_cast<__half2*>(d_KH);
    o[2 * i]     = __floats2half2_rn(v.x, v.y);
    o[2 * i + 1] = __floats2half2_rn(v.z, v.w);
}
__global__ void transV_kernel(const float* __restrict__ V) {
    __shared__ float tile[32][33];
    int b = blockIdx.z, k0 = blockIdx.x * 32, d0 = blockIdx.y * 32;
    int tx = threadIdx.x, ty = threadIdx.y;
    const float* src = V + ((size_t)b * KV_LEN + k0) * HD + d0;
#pragma unroll
    for (int i = 0; i < 32; i += 8) tile[ty + i][tx] = src[(size_t)(ty + i) * HD + tx];
    __syncthreads();
    __half* dst = d_VT + ((size_t)b * HD + d0) * KV_LEN + k0;
#pragma unroll
    for (int i = 0; i < 32; i += 8)
        dst[(size_t)(ty + i) * KV_LEN + tx] = __float2half(tile[tx][ty + i]);
}
__global__ void transPE_kernel(const float* __restrict__ PE) {
    __shared__ float tile[32][33];
    int l0 = blockIdx.x * 32, d0 = blockIdx.y * 32;
    int tx = threadIdx.x, ty = threadIdx.y;
#pragma unroll
    for (int i = 0; i < 32; i += 8)
        tile[ty + i][tx] = PE[(size_t)(d0 + ty + i) * L_SPAN + l0 + tx];
    __syncthreads();
#pragma unroll
    for (int i = 0; i < 32; i += 8)
        d_PET[(size_t)(l0 + ty + i) * HD + d0 + tx] = __float2half(tile[tx][ty + i]);
}

// ---------------- main kernel ----------------
extern "C" __global__ void __launch_bounds__(THREADS, 2)
seq_attn_kernel(float* __restrict__ OUT)
{
    extern __shared__ __align__(16) char smraw[];
    __half*   smH = reinterpret_cast<__half*>(smraw);
    uint32_t* smW = reinterpret_cast<uint32_t*>(smraw);
    float*    smF = reinterpret_cast<float*>(smraw);

    const int tid  = threadIdx.x;
    const int warp = tid >> 5;
    const int lane = tid & 31;
    const int g    = lane >> 2;
    const int tg   = lane & 3;
    const int rg   = warp & 1;        // row group 0..1 (32 rows)
    const int qtr  = warp >> 1;       // column quarter 0..3
    const int m0   = blockIdx.x * BM;
    const int b    = blockIdx.y;

    const int kcb = qtr * 16;         // QK: 16 key cols
    const int dcb = qtr * 32;         // PV: 32 out dims

    const int c16 = tid & 15, r16 = tid >> 4;
    const int c8  = tid & 7,  r8  = tid >> 3;

    // ---- ldmatrix lane addresses (bytes, shared space) ----
    const int lr  = lane & 15;                   // A row within m16
    const int lkh = (lane >> 4) * 8;             // A col offset (halfs)
    const int bnr = ((lane >> 4) << 3) + (lane & 7);   // B row (n) within n16
    const int bkh = ((lane >> 3) & 1) * 8;       // B col offset (halfs)

    const uint32_t aQ0 = (uint32_t)__cvta_generic_to_shared(
        smH + QS_H + (rg * 32 + lr) * 136 + lkh);
    const uint32_t aQ1 = aQ0 + 16 * 136 * 2;
    const uint32_t aK  = (uint32_t)__cvta_generic_to_shared(
        smH + KS_H + (kcb + bnr) * 136 + bkh);
    const uint32_t aP  = (uint32_t)__cvta_generic_to_shared(
        smH + PL_H + (kcb + bnr) * 136 + bkh);
    const uint32_t aV0 = (uint32_t)__cvta_generic_to_shared(
        smH + VT_H + (dcb + bnr) * 72 + bkh);
    const uint32_t aV1 = aV0 + 16 * 72 * 2;
    const uint32_t aB0 = (uint32_t)__cvta_generic_to_shared(
        smH + PB_H + (rg * 32 + lr) * 72 + lkh);
    const uint32_t aB1 = aB0 + 16 * 72 * 2;

    const __half* gK  = d_KH + ((size_t)b * KV_LEN + m0) * HD;
    const __half* gVT = d_VT + (size_t)b * HD * KV_LEN + m0;

    auto issueK = [&](int t) {
#pragma unroll
        for (int i = 0; i < 4; ++i) {
            const int r = r16 + 16 * i;
            uint32_t dst = (uint32_t)__cvta_generic_to_shared(smH + KS_H + r * 136 + 8 * c16);
            CP16(dst, gK + ((size_t)t * BN + r) * HD + 8 * c16);
        }
    };
    auto issueV = [&](int t) {
#pragma unroll
        for (int i = 0; i < 4; ++i) {
            const int d = r8 + 32 * i;
            uint32_t dst = (uint32_t)__cvta_generic_to_shared(smH + VT_H + d * 72 + 8 * c8);
            CP16(dst, gVT + (size_t)d * KV_LEN + t * BN + 8 * c8);
        }
    };
    auto issueP = [&](int t) {
#pragma unroll
        for (int i = 0; i < 4; ++i) {
            const int r = r16 + 16 * i;
            uint32_t dst = (uint32_t)__cvta_generic_to_shared(smH + PL_H + r * 136 + 8 * c16);
            CP16(dst, d_PET + ((size_t)t * BN + r) * HD + 8 * c16);
        }
    };

    // ---- prologue: group A = Q + K(0) + PL(0); group B = V(0) ----
    {
        const __half* gq = d_QH + ((size_t)b * M_TOTAL + m0) * HD;
#pragma unroll
        for (int i = 0; i < 4; ++i) {
            const int r = r16 + 16 * i;
            uint32_t dst = (uint32_t)__cvta_generic_to_shared(smH + QS_H + r * 136 + 8 * c16);
            CP16(dst, gq + (size_t)r * HD + 8 * c16);
        }
        issueK(0); issueP(0);
        CP_COMMIT();
        issueV(0);
        CP_COMMIT();
    }

    float O[2][4][4];
#pragma unroll
    for (int mt = 0; mt < 2; ++mt)
#pragma unroll
        for (int n = 0; n < 4; ++n)
#pragma unroll
            for (int e = 0; e < 4; ++e) O[mt][n][e] = 0.f;

    float m_run[2][2] = {{-1e30f, -1e30f}, {-1e30f, -1e30f}};
    float l_run[2][2] = {{0.f, 0.f}, {0.f, 0.f}};

    uint32_t* Wpb = smW + (PB_H >> 1);

    for (int t = 0; t < NKT; ++t) {
        const bool do_pos = (t < NPOS);

        CP_WAIT1();        // K(t)/PL(t)/(Q) landed; V(t) may still fly
        __syncthreads();   // S1

        // ---- S = Q @ K^T, Spos = Q @ PET (8 k16 steps via ldmatrix) ----
        float s[2][2][4], sp[2][2][4];
#pragma unroll
        for (int mt = 0; mt < 2; ++mt)
#pragma unroll
            for (int n = 0; n < 2; ++n)
#pragma unroll
                for (int e = 0; e < 4; ++e) { s[mt][n][e] = 0.f; sp[mt][n][e] = 0.f; }

#pragma unroll 4
        for (int ks = 0; ks < 8; ++ks) {
            const uint32_t off = ks * 32;
            uint32_t a0[4], a1[4], bk[4];
            LDSM4(a0, aQ0 + off);
            LDSM4(a1, aQ1 + off);
            LDSM4(bk, aK + off);
            mma_f16(s[0][0], a0, bk);     mma_f16(s[0][1], a0, bk + 2);
            mma_f16(s[1][0], a1, bk);     mma_f16(s[1][1], a1, bk + 2);
            if (do_pos) {
                uint32_t bp[4];
                LDSM4(bp, aP + off);
                mma_f16(sp[0][0], a0, bp); mma_f16(sp[0][1], a0, bp + 2);
                mma_f16(sp[1][0], a1, bp); mma_f16(sp[1][1], a1, bp + 2);
            }
        }

        // ---- Spos -> fp32 ring ----
        if (do_pos) {
            const int base = (t & 1) * BN;
            float* rgb = smF + RG_F;
#pragma unroll
            for (int mt = 0; mt < 2; ++mt) {
                const int rr = rg * 32 + mt * 16 + g;
#pragma unroll
                for (int nt = 0; nt < 2; ++nt) {
                    const int c = kcb + nt * 8 + tg * 2;
                    rgb[rr * 132 + base + c]           = sp[mt][nt][0];
                    rgb[rr * 132 + base + c + 1]       = sp[mt][nt][1];
                    rgb[(rr + 8) * 132 + base + c]     = sp[mt][nt][2];
                    rgb[(rr + 8) * 132 + base + c + 1] = sp[mt][nt][3];
                }
            }
        }
        __syncthreads();   // S2: QK consumers done -> K/PL free; ring visible

        // ---- prefetch K/P for t+1 (own commit group) ----
        if (t + 1 < NKT) {
            issueK(t + 1);
            if (t + 1 < NPOS) issueP(t + 1);
            CP_COMMIT();
        }

        // ---- add positional logit, mask window ----
        {
            const float* rgb = smF + RG_F;
#pragma unroll
            for (int mt = 0; mt < 2; ++mt) {
#pragma unroll
                for (int nt = 0; nt < 2; ++nt) {
#pragma unroll
                    for (int e = 0; e < 4; ++e) {
                        const int j = kcb + nt * 8 + tg * 2 + (e & 1);
                        const int r = rg * 32 + mt * 16 + g + ((e < 2) ? 0 : 8);
                        const int l = t * BN + j - r;
                        if (l >= 0 && l < L_SPAN)
                            s[mt][nt][e] += rgb[r * 132 + (l & 127)];
                        else
                            s[mt][nt][e] = -1e30f;
                    }
                }
            }
        }

        // ---- online softmax: local max + cross-quarter exchange ----
        float ml[2][2];
#pragma unroll
        for (int mt = 0; mt < 2; ++mt) {
            ml[mt][0] = fmaxf(fmaxf(s[mt][0][0], s[mt][0][1]), fmaxf(s[mt][1][0], s[mt][1][1]));
            ml[mt][1] = fmaxf(fmaxf(s[mt][0][2], s[mt][0][3]), fmaxf(s[mt][1][2], s[mt][1][3]));
#pragma unroll
            for (int h = 0; h < 2; ++h) {
                ml[mt][h] = fmaxf(ml[mt][h], __shfl_xor_sync(0xffffffffu, ml[mt][h], 1));
                ml[mt][h] = fmaxf(ml[mt][h], __shfl_xor_sync(0xffffffffu, ml[mt][h], 2));
            }
        }
        float* ex = smF + EX_F;
        if (tg == 0) {
#pragma unroll
            for (int mt = 0; mt < 2; ++mt)
#pragma unroll
                for (int h = 0; h < 2; ++h)
                    ex[qtr * BM + rg * 32 + mt * 16 + h * 8 + g] = ml[mt][h];
        }
        __syncthreads();   // S3
#pragma unroll
        for (int mt = 0; mt < 2; ++mt)
#pragma unroll
            for (int h = 0; h < 2; ++h) {
                const int row = rg * 32 + mt * 16 + h * 8 + g;
#pragma unroll
                for (int qq = 0; qq < 4; ++qq)
                    ml[mt][h] = fmaxf(ml[mt][h], ex[qq * BM + row]);
            }

        float al[2][2];
#pragma unroll
        for (int mt = 0; mt < 2; ++mt)
#pragma unroll
            for (int h = 0; h < 2; ++h) {
                const float mn = fmaxf(m_run[mt][h], ml[mt][h]);
                al[mt][h] = __expf(m_run[mt][h] - mn);
                m_run[mt][h] = mn;
            }

#pragma unroll
        for (int mt = 0; mt < 2; ++mt) {
            float ps0 = 0.f, ps1 = 0.f;
#pragma unroll
            for (int nt = 0; nt < 2; ++nt) {
                s[mt][nt][0] = __expf(s[mt][nt][0] - m_run[mt][0]);
                s[mt][nt][1] = __expf(s[mt][nt][1] - m_run[mt][0]);
                s[mt][nt][2] = __expf(s[mt][nt][2] - m_run[mt][1]);
                s[mt][nt][3] = __expf(s[mt][nt][3] - m_run[mt][1]);
                ps0 += s[mt][nt][0] + s[mt][nt][1];
                ps1 += s[mt][nt][2] + s[mt][nt][3];
            }
            l_run[mt][0] = l_run[mt][0] * al[mt][0] + ps0;
            l_run[mt][1] = l_run[mt][1] * al[mt][1] + ps1;
#pragma unroll
            for (int n = 0; n < 4; ++n) {
                O[mt][n][0] *= al[mt][0]; O[mt][n][1] *= al[mt][0];
                O[mt][n][2] *= al[mt][1]; O[mt][n][3] *= al[mt][1];
            }
        }

        // ---- probs -> PB (half2) ----
#pragma unroll
        for (int mt = 0; mt < 2; ++mt) {
            const int rr = rg * 32 + mt * 16 + g;
#pragma unroll
            for (int nt = 0; nt < 2; ++nt) {
                const int wi = qtr * 8 + nt * 4 + tg;
                __half2 h0 = __floats2half2_rn(s[mt][nt][0], s[mt][nt][1]);
                __half2 h1 = __floats2half2_rn(s[mt][nt][2], s[mt][nt][3]);
                Wpb[rr * 36 + wi]       = *reinterpret_cast<uint32_t*>(&h0);
                Wpb[(rr + 8) * 36 + wi] = *reinterpret_cast<uint32_t*>(&h1);
            }
        }

        // V(t) must have landed: only the K/P(t+1) group may remain pending.
        if (t + 1 < NKT) CP_WAIT1(); else CP_WAIT0();
        __syncthreads();   // S4: probs + V(t) visible

        // ---- O += P @ V (4 k16 steps via ldmatrix) ----
#pragma unroll
        for (int ks = 0; ks < 4; ++ks) {
            const uint32_t off = ks * 32;
            uint32_t a0[4], a1[4], bv0[4], bv1[4];
            LDSM4(a0, aB0 + off);
            LDSM4(a1, aB1 + off);
            LDSM4(bv0, aV0 + off);
            LDSM4(bv1, aV1 + off);
            mma_f16(O[0][0], a0, bv0); mma_f16(O[0][1], a0, bv0 + 2);
            mma_f16(O[0][2], a0, bv1); mma_f16(O[0][3], a0, bv1 + 2);
            mma_f16(O[1][0], a1, bv0); mma_f16(O[1][1], a1, bv0 + 2);
            mma_f16(O[1][2], a1, bv1); mma_f16(O[1][3], a1, bv1 + 2);
        }
        __syncthreads();   // S5: V/PB buffers free

        if (t + 1 < NKT) { issueV(t + 1); CP_COMMIT(); }
    }

    // ---- epilogue: quarter-sum reduction, normalize, store ----
#pragma unroll
    for (int mt = 0; mt < 2; ++mt)
#pragma unroll
        for (int h = 0; h < 2; ++h) {
            l_run[mt][h] += __shfl_xor_sync(0xffffffffu, l_run[mt][h], 1);
            l_run[mt][h] += __shfl_xor_sync(0xffffffffu, l_run[mt][h], 2);
        }
    float* ex = smF + EX_F;
    if (tg == 0) {
#pragma unroll
        for (int mt = 0; mt < 2; ++mt)
#pragma unroll
            for (int h = 0; h < 2; ++h)
                ex[qtr * BM + rg * 32 + mt * 16 + h * 8 + g] = l_run[mt][h];
    }
    __syncthreads();
    float inv[2][2];
#pragma unroll
    for (int mt = 0; mt < 2; ++mt)
#pragma unroll
        for (int h = 0; h < 2; ++h) {
            const int row = rg * 32 + mt * 16 + h * 8 + g;
            float tsum = 0.f;
#pragma unroll
            for (int qq = 0; qq < 4; ++qq) tsum += ex[qq * BM + row];
            inv[mt][h] = 1.f / tsum;
        }

    float* go = OUT + ((size_t)b * M_TOTAL + m0) * HD;
#pragma unroll
    for (int mt = 0; mt < 2; ++mt) {
        const int rr = rg * 32 + mt * 16 + g;
#pragma unroll
        for (int nt8 = 0; nt8 < 4; ++nt8) {
            const int c = dcb + nt8 * 8 + tg * 2;
            *reinterpret_cast<float2*>(go + rr * HD + c) =
                make_float2(O[mt][nt8][0] * inv[mt][0], O[mt][nt8][1] * inv[mt][0]);
            *reinterpret_cast<float2*>(go + (rr + 8) * HD + c) =
                make_float2(O[mt][nt8][2] * inv[mt][1], O[mt][nt8][3] * inv[mt][1]);
        }
    }
}

extern "C" void kernel_launch(void* const* d_in, const int* in_sizes, int n_in,
                              void* d_out, int out_size) {
    const float* q  = (const float*)d_in[0];
    const float* k  = (const float*)d_in[1];
    const float* v  = (const float*)d_in[2];
    const float* pe = (const float*)d_in[3];
    float* out = (float*)d_out;

    cvtQ_kernel<<<(BH_N * M_TOTAL * HD / 4) / 256, 256>>>(q);
    cvtK_kernel<<<(size_t)(BH_N * KV_LEN * HD / 4) / 256, 256>>>(k);
    {
        dim3 gt(KV_LEN / 32, HD / 32, BH_N);
        transV_kernel<<<gt, dim3(32, 8)>>>(v);
    }
    {
        dim3 gp(L_SPAN / 32, HD / 32);
        transPE_kernel<<<gp, dim3(32, 8)>>>(pe);
    }

    cudaFuncSetAttribute(seq_attn_kernel,
                         cudaFuncAttributeMaxDynamicSharedMemorySize, SMEM_BYTES);
    dim3 grid(M_TOTAL / BM, BH_N);
    seq_attn_kernel<<<grid, THREADS, SMEM_BYTES>>>(out);
}